// round 16
// baseline (speedup 1.0000x reference)
#include <cuda_runtime.h>
#include <cuda_fp16.h>
#include <cstdint>

#define BB 2
#define TT 2048
#define CC 2048
#define HH 16
#define DD 128
#define MTOT (BB * TT)
#define KTOT CC
#define NQKV 2304
#define QSCALE (0.08838834764831845f * 1.44269504088896340f)  // 1/sqrt(128)*log2e

// ---------------------------------------------------------------------------
// Scratch (fp16 everywhere)
// ---------------------------------------------------------------------------
__device__ __half g_x[(size_t)MTOT * KTOT];       // [m][k]
__device__ __half g_w[(size_t)KTOT * NQKV];       // [k][n] packed wq|wk|wv
__device__ __half g_wo[(size_t)KTOT * CC];        // [k][n]
__device__ float  g_bias[NQKV];

__device__ __half g_Q[(size_t)MTOT * CC];         // [B,H,T,D]
__device__ __half g_K[(size_t)MTOT * DD];         // [B,T,D]
__device__ __half g_V[(size_t)MTOT * DD];         // [B,T,D]
__device__ __half g_O[(size_t)MTOT * CC];         // [B,T,H*D]

// ---------------------------------------------------------------------------
// PTX helpers
// ---------------------------------------------------------------------------
__device__ __forceinline__ uint32_t smem_u32(const void* p) {
    uint32_t a;
    asm("{ .reg .u64 t; cvta.to.shared.u64 t, %1; cvt.u32.u64 %0, t; }"
        : "=r"(a) : "l"(p));
    return a;
}
__device__ __forceinline__ float ex2(float x) {
    float y; asm("ex2.approx.ftz.f32 %0, %1;" : "=f"(y) : "f"(x)); return y;
}

#define LDSM_X4(r0, r1, r2, r3, addr) \
    asm volatile("ldmatrix.sync.aligned.m8n8.x4.shared.b16 {%0,%1,%2,%3}, [%4];" \
                 : "=r"(r0), "=r"(r1), "=r"(r2), "=r"(r3) : "r"(addr))
#define LDSM_X4_T(r0, r1, r2, r3, addr) \
    asm volatile("ldmatrix.sync.aligned.m8n8.x4.trans.shared.b16 {%0,%1,%2,%3}, [%4];" \
                 : "=r"(r0), "=r"(r1), "=r"(r2), "=r"(r3) : "r"(addr))

#define MMA_F16(d, a, b0v, b1v) \
    asm volatile("mma.sync.aligned.m16n8k16.row.col.f32.f16.f16.f32 " \
                 "{%0,%1,%2,%3}, {%4,%5,%6,%7}, {%8,%9}, {%0,%1,%2,%3};" \
                 : "+f"((d)[0]), "+f"((d)[1]), "+f"((d)[2]), "+f"((d)[3]) \
                 : "r"((a)[0]), "r"((a)[1]), "r"((a)[2]), "r"((a)[3]), \
                   "r"(b0v), "r"(b1v))

#define CP16(dst, src) \
    asm volatile("cp.async.cg.shared.global [%0], [%1], 16;" :: "r"(dst), "l"(src))
#define CP_COMMIT() asm volatile("cp.async.commit_group;" ::: "memory")
#define CP_WAIT(n)  asm volatile("cp.async.wait_group %0;" :: "n"(n) : "memory")

__device__ __forceinline__ uint32_t packh2(float x, float y) {
    __half2 h = __floats2half2_rn(x, y);
    return *(uint32_t*)&h;
}

// ---------------------------------------------------------------------------
// prep: fp32 -> fp16 converts + bias pack.
// ---------------------------------------------------------------------------
__global__ __launch_bounds__(256) void prep_kernel(
    const float* __restrict__ x,  const float* __restrict__ wq,
    const float* __restrict__ wk, const float* __restrict__ wv,
    const float* __restrict__ wo,
    const float* __restrict__ qb, const float* __restrict__ kb,
    const float* __restrict__ vb)
{
    int blk = blockIdx.x, tid = threadIdx.x;
    if (blk < 8192) {                     // x contiguous
        int i = blk * 256 + tid;
        float4 v = ((const float4*)x)[i];
        ((uint2*)g_x)[i] = make_uint2(packh2(v.x, v.y), packh2(v.z, v.w));
    } else if (blk < 12288) {             // wq -> cols 0..2047 of g_w
        int i = (blk - 8192) * 256 + tid;
        int row = i >> 9, col = (i << 2) & 2047;
        float4 v = ((const float4*)wq)[i];
        *(uint2*)(g_w + (size_t)row * NQKV + col) =
            make_uint2(packh2(v.x, v.y), packh2(v.z, v.w));
    } else if (blk < 12544) {             // wk -> cols 2048..2175
        int i = (blk - 12288) * 256 + tid;
        int row = i >> 5, col = (i << 2) & 127;
        float4 v = ((const float4*)wk)[i];
        *(uint2*)(g_w + (size_t)row * NQKV + 2048 + col) =
            make_uint2(packh2(v.x, v.y), packh2(v.z, v.w));
    } else if (blk < 12800) {             // wv -> cols 2176..2303
        int i = (blk - 12544) * 256 + tid;
        int row = i >> 5, col = (i << 2) & 127;
        float4 v = ((const float4*)wv)[i];
        *(uint2*)(g_w + (size_t)row * NQKV + 2176 + col) =
            make_uint2(packh2(v.x, v.y), packh2(v.z, v.w));
    } else if (blk < 16896) {             // wo contiguous
        int i = (blk - 12800) * 256 + tid;
        float4 v = ((const float4*)wo)[i];
        ((uint2*)g_wo)[i] = make_uint2(packh2(v.x, v.y), packh2(v.z, v.w));
    } else {                              // bias
        int i = (blk - 16896) * 256 + tid;
        if (i < 2048)      g_bias[i] = qb[i];
        else if (i < 2176) g_bias[i] = kb[i - 2048];
        else if (i < 2304) g_bias[i] = vb[i - 2176];
    }
}

// ---------------------------------------------------------------------------
// fp16 GEMM machinery: BM=128 BN=128 BK=32, 128 thr (4 warps, 64x64 tiles),
// cp.async 4-stage (16KB/stage = A 8K | B 8K) = 64KB smem -> 3 CTA/SM.
// k-accumulation order identical to R14 (bitwise-same results).
// ---------------------------------------------------------------------------
#define STG_BYTES 16384
#define G2SMEM (4 * STG_BYTES)
#define NITER (KTOT / 32)   // 64
#define GTHR 128

__device__ __forceinline__ uint32_t a_off(int r, int c) {
    return (uint32_t)(r * 64 + ((c ^ ((r >> 1) & 3)) << 4));
}
__device__ __forceinline__ uint32_t b_off(int r, int c) {
    return (uint32_t)(r * 256 + ((c ^ (r & 7)) << 4));
}

__device__ __forceinline__ void g2s_issue(
    uint32_t stg, const __half* __restrict__ A, const __half* __restrict__ W,
    int N, int m0, int n0, int k0, int tid)
{
#pragma unroll
    for (int p = 0; p < 4; p++) {
        int cid = p * GTHR + tid;
        int r = cid >> 2, c = cid & 3;
        CP16(stg + a_off(r, c), A + (size_t)(m0 + r) * KTOT + k0 + c * 8);
    }
#pragma unroll
    for (int p = 0; p < 4; p++) {
        int cid = p * GTHR + tid;
        int r = cid >> 4, c = cid & 15;
        CP16(stg + 8192 + b_off(r, c), W + (size_t)(k0 + r) * N + n0 + c * 8);
    }
}

__device__ __forceinline__ void gemm_mainloop(
    uint32_t sb, const __half* A, const __half* W,
    int N, int m0, int n0, int tid, int lane, int wm, int wn, float acc[4][8][4])
{
    const int lrow = lane & 15;
    const int lsel = lane >> 4;

    g2s_issue(sb, A, W, N, m0, n0, 0, tid);
    CP_COMMIT();
    g2s_issue(sb + STG_BYTES, A, W, N, m0, n0, 32, tid);
    CP_COMMIT();
    g2s_issue(sb + 2 * STG_BYTES, A, W, N, m0, n0, 64, tid);
    CP_COMMIT();

    for (int it = 0; it < NITER; it++) {
        if (it + 2 < NITER)      CP_WAIT(2);
        else if (it + 1 < NITER) CP_WAIT(1);
        else                     CP_WAIT(0);
        __syncthreads();
        if (it + 3 < NITER) {
            g2s_issue(sb + ((it + 3) & 3) * STG_BYTES, A, W, N,
                      m0, n0, (it + 3) * 32, tid);
            CP_COMMIT();
        }

        const uint32_t stA = sb + (uint32_t)(it & 3) * STG_BYTES;
        const uint32_t stB = stA + 8192;

#pragma unroll
        for (int ks = 0; ks < 2; ks++) {
            uint32_t a[4][4];
#pragma unroll
            for (int mf = 0; mf < 4; mf++) {
                uint32_t addr = stA + a_off(wm * 64 + mf * 16 + lrow, ks * 2 + lsel);
                LDSM_X4(a[mf][0], a[mf][1], a[mf][2], a[mf][3], addr);
            }
#pragma unroll
            for (int nj = 0; nj < 4; nj++) {
                uint32_t baddr = stB + b_off(ks * 16 + lrow, wn * 8 + nj * 2 + lsel);
                uint32_t b[4];
                LDSM_X4_T(b[0], b[1], b[2], b[3], baddr);
#pragma unroll
                for (int mf = 0; mf < 4; mf++) {
                    MMA_F16(acc[mf][2 * nj],     a[mf], b[0], b[1]);
                    MMA_F16(acc[mf][2 * nj + 1], a[mf], b[2], b[3]);
                }
            }
        }
    }
}

// ---------------------------------------------------------------------------
// Fused QKV GEMM: x @ [wq|wk|wv] + bias (N=2304, 18 CTA cols x 128).
// ---------------------------------------------------------------------------
__global__ __launch_bounds__(GTHR, 3)
void gemm_qkv(const float* __restrict__ cs, const float* __restrict__ sn)
{
    extern __shared__ char sm[];
    const uint32_t sb = smem_u32(sm);
    const int tid  = threadIdx.x;
    const int lane = tid & 31;
    const int wid  = tid >> 5;
    const int wm   = wid >> 1;
    const int wn   = wid & 1;
    const int m0   = blockIdx.y * 128;
    const int n0   = blockIdx.x * 128;

    float acc[4][8][4];
#pragma unroll
    for (int i = 0; i < 4; i++)
#pragma unroll
        for (int j = 0; j < 8; j++)
#pragma unroll
            for (int q = 0; q < 4; q++) acc[i][j][q] = 0.f;

    gemm_mainloop(sb, g_x, g_w, NQKV, m0, n0, tid, lane, wm, wn, acc);

    const int g = lane >> 2, t = lane & 3;
#pragma unroll
    for (int mf = 0; mf < 4; mf++) {
        int row0 = m0 + wm * 64 + mf * 16 + g;
#pragma unroll
        for (int nt = 0; nt < 8; nt++) {
            int col = n0 + wn * 64 + nt * 8 + 2 * t;
            float2 bi = *(const float2*)(g_bias + col);
            float a0 = acc[mf][nt][0] + bi.x, a1 = acc[mf][nt][1] + bi.y;
            float a2 = acc[mf][nt][2] + bi.x, a3 = acc[mf][nt][3] + bi.y;
            if (col < 2048) {
                // Q: RoPE + scale -> fp16 [B,H,T,D]
                int f = (col & 127) >> 1;
#pragma unroll
                for (int rr = 0; rr < 2; rr++) {
                    int r = row0 + rr * 8;
                    int tloc = r & (TT - 1);
                    float c = cs[tloc * 64 + f], s = sn[tloc * 64 + f];
                    float re = rr ? a2 : a0, im = rr ? a3 : a1;
                    float ore = (re * c - im * s) * QSCALE;
                    float oim = (re * s + im * c) * QSCALE;
                    int bq = r >> 11, hq = col >> 7;
                    size_t idx = ((size_t)(bq * HH + hq) * TT + tloc) * DD + (col & 127);
                    *(uint32_t*)(g_Q + idx) = packh2(ore, oim);
                }
            } else if (col < 2176) {
                int colp = col - 2048;
                int f = colp >> 1;
#pragma unroll
                for (int rr = 0; rr < 2; rr++) {
                    int r = row0 + rr * 8;
                    int tloc = r & (TT - 1);
                    float c = cs[tloc * 64 + f], s = sn[tloc * 64 + f];
                    float re = rr ? a2 : a0, im = rr ? a3 : a1;
                    *(uint32_t*)(g_K + (size_t)r * DD + colp) =
                        packh2(re * c - im * s, re * s + im * c);
                }
            } else {
                int colp = col - 2176;
                *(uint32_t*)(g_V + (size_t)row0 * DD + colp)       = packh2(a0, a1);
                *(uint32_t*)(g_V + (size_t)(row0 + 8) * DD + colp) = packh2(a2, a3);
            }
        }
    }
}

// ---------------------------------------------------------------------------
// Output GEMM: out = O @ wo + bias (fp32 out, N=2048)
// ---------------------------------------------------------------------------
__global__ __launch_bounds__(GTHR, 3)
void gemm_out(const float* __restrict__ bias, float* __restrict__ OutF)
{
    extern __shared__ char sm[];
    const uint32_t sb = smem_u32(sm);
    const int tid  = threadIdx.x;
    const int lane = tid & 31;
    const int wid  = tid >> 5;
    const int wm   = wid >> 1;
    const int wn   = wid & 1;
    const int m0   = blockIdx.y * 128;
    const int n0   = blockIdx.x * 128;

    float acc[4][8][4];
#pragma unroll
    for (int i = 0; i < 4; i++)
#pragma unroll
        for (int j = 0; j < 8; j++)
#pragma unroll
            for (int q = 0; q < 4; q++) acc[i][j][q] = 0.f;

    gemm_mainloop(sb, g_O, g_wo, CC, m0, n0, tid, lane, wm, wn, acc);

    const int g = lane >> 2, t = lane & 3;
#pragma unroll
    for (int mf = 0; mf < 4; mf++) {
        int row0 = m0 + wm * 64 + mf * 16 + g;
#pragma unroll
        for (int nt = 0; nt < 8; nt++) {
            int col = n0 + wn * 64 + nt * 8 + 2 * t;
            float2 bi = *(const float2*)(bias + col);
            *(float2*)(OutF + (size_t)row0 * CC + col) =
                make_float2(acc[mf][nt][0] + bi.x, acc[mf][nt][1] + bi.y);
            *(float2*)(OutF + (size_t)(row0 + 8) * CC + col) =
                make_float2(acc[mf][nt][2] + bi.x, acc[mf][nt][3] + bi.y);
        }
    }
}

// ---------------------------------------------------------------------------
// Flash attention fp16 (R14 unchanged): BM=64, BN=32, D=128, 48KB, 3 CTA/SM.
// ---------------------------------------------------------------------------
#define AKV(s) (16384u + (uint32_t)(s) * 16384u)
#define A_SMEM 49152

__device__ __forceinline__ uint32_t toff(int r, int c) {
    return (uint32_t)(r * 256 + ((c ^ (r & 7)) << 4));
}

__global__ __launch_bounds__(128, 3) void attn_mma()
{
    extern __shared__ char sm[];
    const uint32_t sb = smem_u32(sm);
    const int tid = threadIdx.x, lane = tid & 31, w = tid >> 5;
    const int id = blockIdx.x;
    const int bx = (TT / 64 - 1) - (id >> 5);
    const int hb = id & 31;
    const int h  = hb & 15;
    const int b  = hb >> 4;
    const int i0 = bx * 64;
    const int jtmax = 2 * bx + 1;

    const size_t qbase  = ((size_t)(b * HH + h) * TT + i0) * DD;
    const size_t kvbase = (size_t)b * TT * DD;

#pragma unroll
    for (int i = 0; i < 8; i++) {
        int cid = i * 128 + tid;
        int r = cid >> 4, c = cid & 15;
        CP16(sb + toff(r, c), g_Q + qbase + (size_t)r * DD + c * 8);
    }
#pragma unroll
    for (int i = 0; i < 4; i++) {
        int cid = i * 128 + tid;
        int r = cid >> 4, c = cid & 15;
        size_t gs = kvbase + (size_t)r * DD + c * 8;
        uint32_t off = toff(r, c);
        CP16(sb + AKV(0) + off,        g_K + gs);
        CP16(sb + AKV(0) + 8192 + off, g_V + gs);
    }
    CP_COMMIT();

    const int lrA = lane & 15;
    const int lsA = lane >> 4;
    const int lrB = (lane & 7) + ((lane >> 4) << 3);
    const int csB = (lane >> 3) & 1;
    const int g = lane >> 2, t = lane & 3;

    float oa[16][4];
#pragma unroll
    for (int i = 0; i < 16; i++)
#pragma unroll
        for (int j = 0; j < 4; j++) oa[i][j] = 0.f;
    float m0r = -1e30f, m1r = -1e30f, l0r = 0.f, l1r = 0.f;

    for (int jt = 0; jt <= jtmax; jt++) {
        if (jt > 0) __syncthreads();
        if (jt + 1 <= jtmax) {
            uint32_t stg = AKV((jt + 1) & 1);
#pragma unroll
            for (int i = 0; i < 4; i++) {
                int cid = i * 128 + tid;
                int r = cid >> 4, c = cid & 15;
                size_t gs = kvbase + (size_t)((jt + 1) * 32 + r) * DD + c * 8;
                uint32_t off = toff(r, c);
                CP16(sb + stg + off,        g_K + gs);
                CP16(sb + stg + 8192 + off, g_V + gs);
            }
            CP_COMMIT();
            CP_WAIT(1);
        } else {
            CP_WAIT(0);
        }
        __syncthreads();

        if (32 * jt > i0 + 16 * w + 15) continue;

        const uint32_t kvs = sb + AKV(jt & 1);

        float sa[4][4];
#pragma unroll
        for (int i = 0; i < 4; i++)
#pragma unroll
            for (int j = 0; j < 4; j++) sa[i][j] = 0.f;

#pragma unroll
        for (int ks = 0; ks < 8; ks++) {
            uint32_t a[4];
            LDSM_X4(a[0], a[1], a[2], a[3],
                    sb + toff(16 * w + lrA, 2 * ks + lsA));
#pragma unroll
            for (int np = 0; np < 2; np++) {
                uint32_t k[4];
                LDSM_X4(k[0], k[1], k[2], k[3],
                        kvs + toff(np * 16 + lrB, 2 * ks + csB));
                MMA_F16(sa[2 * np],     a, k[0], k[1]);
                MMA_F16(sa[2 * np + 1], a, k[2], k[3]);
            }
        }

        if (32 * jt + 31 > i0 + 16 * w) {
            int r0g = i0 + 16 * w + g;
#pragma unroll
            for (int nf = 0; nf < 4; nf++) {
                int cg = 32 * jt + nf * 8 + 2 * t;
                if (cg     > r0g)     sa[nf][0] = -1e30f;
                if (cg + 1 > r0g)     sa[nf][1] = -1e30f;
                if (cg     > r0g + 8) sa[nf][2] = -1e30f;
                if (cg + 1 > r0g + 8) sa[nf][3] = -1e30f;
            }
        }

        float mx0 = -1e30f, mx1 = -1e30f;
#pragma unroll
        for (int nf = 0; nf < 4; nf++) {
            mx0 = fmaxf(mx0, fmaxf(sa[nf][0], sa[nf][1]));
            mx1 = fmaxf(mx1, fmaxf(sa[nf][2], sa[nf][3]));
        }
        mx0 = fmaxf(mx0, __shfl_xor_sync(0xffffffffu, mx0, 1));
        mx0 = fmaxf(mx0, __shfl_xor_sync(0xffffffffu, mx0, 2));
        mx1 = fmaxf(mx1, __shfl_xor_sync(0xffffffffu, mx1, 1));
        mx1 = fmaxf(mx1, __shfl_xor_sync(0xffffffffu, mx1, 2));
        float mn0 = fmaxf(m0r, mx0), mn1 = fmaxf(m1r, mx1);

        float sum0 = 0.f, sum1 = 0.f;
#pragma unroll
        for (int nf = 0; nf < 4; nf++) {
            sa[nf][0] = ex2(sa[nf][0] - mn0);
            sa[nf][1] = ex2(sa[nf][1] - mn0);
            sa[nf][2] = ex2(sa[nf][2] - mn1);
            sa[nf][3] = ex2(sa[nf][3] - mn1);
            sum0 += sa[nf][0] + sa[nf][1];
            sum1 += sa[nf][2] + sa[nf][3];
        }
        sum0 += __shfl_xor_sync(0xffffffffu, sum0, 1);
        sum0 += __shfl_xor_sync(0xffffffffu, sum0, 2);
        sum1 += __shfl_xor_sync(0xffffffffu, sum1, 1);
        sum1 += __shfl_xor_sync(0xffffffffu, sum1, 2);

        float scl0 = ex2(m0r - mn0), scl1 = ex2(m1r - mn1);
        l0r = l0r * scl0 + sum0;
        l1r = l1r * scl1 + sum1;
        m0r = mn0; m1r = mn1;

#pragma unroll
        for (int nf = 0; nf < 16; nf++) {
            oa[nf][0] *= scl0; oa[nf][1] *= scl0;
            oa[nf][2] *= scl1; oa[nf][3] *= scl1;
        }

#pragma unroll
        for (int s = 0; s < 2; s++) {
            uint32_t aP[4];
            aP[0] = packh2(sa[2 * s][0],     sa[2 * s][1]);
            aP[1] = packh2(sa[2 * s][2],     sa[2 * s][3]);
            aP[2] = packh2(sa[2 * s + 1][0], sa[2 * s + 1][1]);
            aP[3] = packh2(sa[2 * s + 1][2], sa[2 * s + 1][3]);
#pragma unroll
            for (int np = 0; np < 8; np++) {
                uint32_t v[4];
                LDSM_X4_T(v[0], v[1], v[2], v[3],
                          kvs + 8192 + toff(s * 16 + lrA, 2 * np + lsA));
                MMA_F16(oa[2 * np],     aP, v[0], v[1]);
                MMA_F16(oa[2 * np + 1], aP, v[2], v[3]);
            }
        }
    }

    float inv0 = 1.f / l0r, inv1 = 1.f / l1r;
    size_t or0 = (size_t)(b * TT + i0 + 16 * w + g) * CC + h * DD;
    size_t or1 = or0 + (size_t)8 * CC;
#pragma unroll
    for (int nf = 0; nf < 16; nf++) {
        int col = nf * 8 + 2 * t;
        *(uint32_t*)(g_O + or0 + col) = packh2(oa[nf][0] * inv0, oa[nf][1] * inv0);
        *(uint32_t*)(g_O + or1 + col) = packh2(oa[nf][2] * inv1, oa[nf][3] * inv1);
    }
}

// ---------------------------------------------------------------------------
extern "C" void kernel_launch(void* const* d_in, const int* in_sizes, int n_in,
                              void* d_out, int out_size)
{
    const float* x    = (const float*)d_in[0];
    const float* fcos = (const float*)d_in[1];
    const float* fsin = (const float*)d_in[2];
    const float* wq   = (const float*)d_in[4];
    const float* wqb  = (const float*)d_in[5];
    const float* wk   = (const float*)d_in[6];
    const float* wkb  = (const float*)d_in[7];
    const float* wv   = (const float*)d_in[8];
    const float* wvb  = (const float*)d_in[9];
    const float* wo   = (const float*)d_in[10];
    const float* wob  = (const float*)d_in[11];
    float* out = (float*)d_out;

    cudaFuncSetAttribute(gemm_qkv, cudaFuncAttributeMaxDynamicSharedMemorySize, G2SMEM);
    cudaFuncSetAttribute(gemm_out, cudaFuncAttributeMaxDynamicSharedMemorySize, G2SMEM);
    cudaFuncSetAttribute(attn_mma, cudaFuncAttributeMaxDynamicSharedMemorySize, A_SMEM);

    // 1. fp32 -> fp16 converts + bias pack
    prep_kernel<<<16905, 256>>>(x, wq, wk, wv, wo, wqb, wkb, wvb);

    // 2. fused QKV projection (BK=32, 4-stage, 3 CTA/SM)
    gemm_qkv<<<dim3(NQKV / 128, MTOT / 128), GTHR, G2SMEM>>>(fcos, fsin);

    // 3. flash attention (fp16, 3 CTAs/SM, heavy-first)
    attn_mma<<<1024, 128, A_SMEM>>>();

    // 4. output projection -> d_out (BK=32, 4-stage, 3 CTA/SM)
    gemm_out<<<dim3(CC / 128, MTOT / 128), GTHR, G2SMEM>>>(wob, out);
}

// round 17
// speedup vs baseline: 1.0503x; 1.0503x over previous
#include <cuda_runtime.h>
#include <cuda_fp16.h>
#include <cstdint>

#define BB 2
#define TT 2048
#define CC 2048
#define HH 16
#define DD 128
#define MTOT (BB * TT)
#define KTOT CC
#define NQKV 2304
#define QSCALE (0.08838834764831845f * 1.44269504088896340f)  // 1/sqrt(128)*log2e

// ---------------------------------------------------------------------------
// Scratch (fp16 everywhere)
// ---------------------------------------------------------------------------
__device__ __half g_x[(size_t)MTOT * KTOT];       // [m][k]
__device__ __half g_w[(size_t)KTOT * NQKV];       // [k][n] packed wq|wk|wv
__device__ __half g_wo[(size_t)KTOT * CC];        // [k][n]
__device__ float  g_bias[NQKV];

__device__ __half g_Q[(size_t)MTOT * CC];         // [B,H,T,D]
__device__ __half g_K[(size_t)MTOT * DD];         // [B,T,D]
__device__ __half g_V[(size_t)MTOT * DD];         // [B,T,D]
__device__ __half g_O[(size_t)MTOT * CC];         // [B,T,H*D]

// ---------------------------------------------------------------------------
// PTX helpers
// ---------------------------------------------------------------------------
__device__ __forceinline__ uint32_t smem_u32(const void* p) {
    uint32_t a;
    asm("{ .reg .u64 t; cvta.to.shared.u64 t, %1; cvt.u32.u64 %0, t; }"
        : "=r"(a) : "l"(p));
    return a;
}
__device__ __forceinline__ float ex2(float x) {
    float y; asm("ex2.approx.ftz.f32 %0, %1;" : "=f"(y) : "f"(x)); return y;
}

#define LDSM_X4(r0, r1, r2, r3, addr) \
    asm volatile("ldmatrix.sync.aligned.m8n8.x4.shared.b16 {%0,%1,%2,%3}, [%4];" \
                 : "=r"(r0), "=r"(r1), "=r"(r2), "=r"(r3) : "r"(addr))
#define LDSM_X4_T(r0, r1, r2, r3, addr) \
    asm volatile("ldmatrix.sync.aligned.m8n8.x4.trans.shared.b16 {%0,%1,%2,%3}, [%4];" \
                 : "=r"(r0), "=r"(r1), "=r"(r2), "=r"(r3) : "r"(addr))

#define MMA_F16(d, a, b0v, b1v) \
    asm volatile("mma.sync.aligned.m16n8k16.row.col.f32.f16.f16.f32 " \
                 "{%0,%1,%2,%3}, {%4,%5,%6,%7}, {%8,%9}, {%0,%1,%2,%3};" \
                 : "+f"((d)[0]), "+f"((d)[1]), "+f"((d)[2]), "+f"((d)[3]) \
                 : "r"((a)[0]), "r"((a)[1]), "r"((a)[2]), "r"((a)[3]), \
                   "r"(b0v), "r"(b1v))

#define CP16(dst, src) \
    asm volatile("cp.async.cg.shared.global [%0], [%1], 16;" :: "r"(dst), "l"(src))
#define CP_COMMIT() asm volatile("cp.async.commit_group;" ::: "memory")
#define CP_WAIT(n)  asm volatile("cp.async.wait_group %0;" :: "n"(n) : "memory")

__device__ __forceinline__ uint32_t packh2(float x, float y) {
    __half2 h = __floats2half2_rn(x, y);
    return *(uint32_t*)&h;
}

// ---------------------------------------------------------------------------
// prep: fp32 -> fp16 converts + bias pack.
// ---------------------------------------------------------------------------
__global__ __launch_bounds__(256) void prep_kernel(
    const float* __restrict__ x,  const float* __restrict__ wq,
    const float* __restrict__ wk, const float* __restrict__ wv,
    const float* __restrict__ wo,
    const float* __restrict__ qb, const float* __restrict__ kb,
    const float* __restrict__ vb)
{
    int blk = blockIdx.x, tid = threadIdx.x;
    if (blk < 8192) {                     // x contiguous
        int i = blk * 256 + tid;
        float4 v = ((const float4*)x)[i];
        ((uint2*)g_x)[i] = make_uint2(packh2(v.x, v.y), packh2(v.z, v.w));
    } else if (blk < 12288) {             // wq -> cols 0..2047 of g_w
        int i = (blk - 8192) * 256 + tid;
        int row = i >> 9, col = (i << 2) & 2047;
        float4 v = ((const float4*)wq)[i];
        *(uint2*)(g_w + (size_t)row * NQKV + col) =
            make_uint2(packh2(v.x, v.y), packh2(v.z, v.w));
    } else if (blk < 12544) {             // wk -> cols 2048..2175
        int i = (blk - 12288) * 256 + tid;
        int row = i >> 5, col = (i << 2) & 127;
        float4 v = ((const float4*)wk)[i];
        *(uint2*)(g_w + (size_t)row * NQKV + 2048 + col) =
            make_uint2(packh2(v.x, v.y), packh2(v.z, v.w));
    } else if (blk < 12800) {             // wv -> cols 2176..2303
        int i = (blk - 12544) * 256 + tid;
        int row = i >> 5, col = (i << 2) & 127;
        float4 v = ((const float4*)wv)[i];
        *(uint2*)(g_w + (size_t)row * NQKV + 2176 + col) =
            make_uint2(packh2(v.x, v.y), packh2(v.z, v.w));
    } else if (blk < 16896) {             // wo contiguous
        int i = (blk - 12800) * 256 + tid;
        float4 v = ((const float4*)wo)[i];
        ((uint2*)g_wo)[i] = make_uint2(packh2(v.x, v.y), packh2(v.z, v.w));
    } else {                              // bias
        int i = (blk - 16896) * 256 + tid;
        if (i < 2048)      g_bias[i] = qb[i];
        else if (i < 2176) g_bias[i] = kb[i - 2048];
        else if (i < 2304) g_bias[i] = vb[i - 2176];
    }
}

// ---------------------------------------------------------------------------
// fp16 GEMM machinery: BM=128 BN=128 BK=64, 128 thr (4 warps, 64x64 tiles),
// cp.async 3-stage (32KB/stage = A 16K | B 16K), 96KB smem, 2 CTA/SM.
// Per ks-group: ALL 8 LDSMs (A x4, B x4) hoisted before the 32 MMAs so the
// LDS latency pipelines. MMA order per accumulator unchanged (bitwise-same).
// ---------------------------------------------------------------------------
#define STG_BYTES 32768
#define G2SMEM (3 * STG_BYTES)
#define NITER (KTOT / 64)   // 32
#define GTHR 128

// A tile [128 rows][64 k]: 128B/row, 8 chunks of 16B, XOR-8 swizzle
__device__ __forceinline__ uint32_t a_off(int r, int c) {
    return (uint32_t)(r * 128 + ((c ^ (r & 7)) << 4));
}
// B tile [64 k][128 n]: 256B/row, 16 chunks of 16B, XOR-8 swizzle
__device__ __forceinline__ uint32_t b_off(int r, int c) {
    return (uint32_t)(r * 256 + ((c ^ (r & 7)) << 4));
}

__device__ __forceinline__ void g2s_issue(
    uint32_t stg, const __half* __restrict__ A, const __half* __restrict__ W,
    int N, int m0, int n0, int k0, int tid)
{
#pragma unroll
    for (int p = 0; p < 8; p++) {
        int cid = p * GTHR + tid;
        int r = cid >> 3, c = cid & 7;
        CP16(stg + a_off(r, c), A + (size_t)(m0 + r) * KTOT + k0 + c * 8);
    }
#pragma unroll
    for (int p = 0; p < 8; p++) {
        int cid = p * GTHR + tid;
        int r = cid >> 4, c = cid & 15;
        CP16(stg + 16384 + b_off(r, c), W + (size_t)(k0 + r) * N + n0 + c * 8);
    }
}

__device__ __forceinline__ void gemm_mainloop(
    uint32_t sb, const __half* A, const __half* W,
    int N, int m0, int n0, int tid, int lane, int wm, int wn, float acc[4][8][4])
{
    const int lrow = lane & 15;
    const int lsel = lane >> 4;

    g2s_issue(sb, A, W, N, m0, n0, 0, tid);
    CP_COMMIT();
    g2s_issue(sb + STG_BYTES, A, W, N, m0, n0, 64, tid);
    CP_COMMIT();

    for (int it = 0; it < NITER; it++) {
        if (it == NITER - 1) CP_WAIT(0); else CP_WAIT(1);
        __syncthreads();
        if (it + 2 < NITER) {
            g2s_issue(sb + ((it + 2) % 3) * STG_BYTES, A, W, N,
                      m0, n0, (it + 2) * 64, tid);
            CP_COMMIT();
        }

        const uint32_t stA = sb + (uint32_t)(it % 3) * STG_BYTES;
        const uint32_t stB = stA + 16384;

#pragma unroll
        for (int ks = 0; ks < 4; ks++) {
            uint32_t a[4][4], b[4][4];
            // hoisted loads: 8 independent LDSMs pipeline their latency
#pragma unroll
            for (int mf = 0; mf < 4; mf++) {
                uint32_t addr = stA + a_off(wm * 64 + mf * 16 + lrow, ks * 2 + lsel);
                LDSM_X4(a[mf][0], a[mf][1], a[mf][2], a[mf][3], addr);
            }
#pragma unroll
            for (int nj = 0; nj < 4; nj++) {
                uint32_t baddr = stB + b_off(ks * 16 + lrow, wn * 8 + nj * 2 + lsel);
                LDSM_X4_T(b[nj][0], b[nj][1], b[nj][2], b[nj][3], baddr);
            }
#pragma unroll
            for (int nj = 0; nj < 4; nj++) {
#pragma unroll
                for (int mf = 0; mf < 4; mf++) {
                    MMA_F16(acc[mf][2 * nj],     a[mf], b[nj][0], b[nj][1]);
                    MMA_F16(acc[mf][2 * nj + 1], a[mf], b[nj][2], b[nj][3]);
                }
            }
        }
    }
}

// ---------------------------------------------------------------------------
// Fused QKV GEMM: x @ [wq|wk|wv] + bias (N=2304, 18 CTA cols x 128).
// ---------------------------------------------------------------------------
__global__ __launch_bounds__(GTHR, 2)
void gemm_qkv(const float* __restrict__ cs, const float* __restrict__ sn)
{
    extern __shared__ char sm[];
    const uint32_t sb = smem_u32(sm);
    const int tid  = threadIdx.x;
    const int lane = tid & 31;
    const int wid  = tid >> 5;
    const int wm   = wid >> 1;
    const int wn   = wid & 1;
    const int m0   = blockIdx.y * 128;
    const int n0   = blockIdx.x * 128;

    float acc[4][8][4];
#pragma unroll
    for (int i = 0; i < 4; i++)
#pragma unroll
        for (int j = 0; j < 8; j++)
#pragma unroll
            for (int q = 0; q < 4; q++) acc[i][j][q] = 0.f;

    gemm_mainloop(sb, g_x, g_w, NQKV, m0, n0, tid, lane, wm, wn, acc);

    const int g = lane >> 2, t = lane & 3;
#pragma unroll
    for (int mf = 0; mf < 4; mf++) {
        int row0 = m0 + wm * 64 + mf * 16 + g;
#pragma unroll
        for (int nt = 0; nt < 8; nt++) {
            int col = n0 + wn * 64 + nt * 8 + 2 * t;
            float2 bi = *(const float2*)(g_bias + col);
            float a0 = acc[mf][nt][0] + bi.x, a1 = acc[mf][nt][1] + bi.y;
            float a2 = acc[mf][nt][2] + bi.x, a3 = acc[mf][nt][3] + bi.y;
            if (col < 2048) {
                // Q: RoPE + scale -> fp16 [B,H,T,D]
                int f = (col & 127) >> 1;
#pragma unroll
                for (int rr = 0; rr < 2; rr++) {
                    int r = row0 + rr * 8;
                    int tloc = r & (TT - 1);
                    float c = cs[tloc * 64 + f], s = sn[tloc * 64 + f];
                    float re = rr ? a2 : a0, im = rr ? a3 : a1;
                    float ore = (re * c - im * s) * QSCALE;
                    float oim = (re * s + im * c) * QSCALE;
                    int bq = r >> 11, hq = col >> 7;
                    size_t idx = ((size_t)(bq * HH + hq) * TT + tloc) * DD + (col & 127);
                    *(uint32_t*)(g_Q + idx) = packh2(ore, oim);
                }
            } else if (col < 2176) {
                int colp = col - 2048;
                int f = colp >> 1;
#pragma unroll
                for (int rr = 0; rr < 2; rr++) {
                    int r = row0 + rr * 8;
                    int tloc = r & (TT - 1);
                    float c = cs[tloc * 64 + f], s = sn[tloc * 64 + f];
                    float re = rr ? a2 : a0, im = rr ? a3 : a1;
                    *(uint32_t*)(g_K + (size_t)r * DD + colp) =
                        packh2(re * c - im * s, re * s + im * c);
                }
            } else {
                int colp = col - 2176;
                *(uint32_t*)(g_V + (size_t)row0 * DD + colp)       = packh2(a0, a1);
                *(uint32_t*)(g_V + (size_t)(row0 + 8) * DD + colp) = packh2(a2, a3);
            }
        }
    }
}

// ---------------------------------------------------------------------------
// Output GEMM: out = O @ wo + bias (fp32 out, N=2048)
// ---------------------------------------------------------------------------
__global__ __launch_bounds__(GTHR, 2)
void gemm_out(const float* __restrict__ bias, float* __restrict__ OutF)
{
    extern __shared__ char sm[];
    const uint32_t sb = smem_u32(sm);
    const int tid  = threadIdx.x;
    const int lane = tid & 31;
    const int wid  = tid >> 5;
    const int wm   = wid >> 1;
    const int wn   = wid & 1;
    const int m0   = blockIdx.y * 128;
    const int n0   = blockIdx.x * 128;

    float acc[4][8][4];
#pragma unroll
    for (int i = 0; i < 4; i++)
#pragma unroll
        for (int j = 0; j < 8; j++)
#pragma unroll
            for (int q = 0; q < 4; q++) acc[i][j][q] = 0.f;

    gemm_mainloop(sb, g_O, g_wo, CC, m0, n0, tid, lane, wm, wn, acc);

    const int g = lane >> 2, t = lane & 3;
#pragma unroll
    for (int mf = 0; mf < 4; mf++) {
        int row0 = m0 + wm * 64 + mf * 16 + g;
#pragma unroll
        for (int nt = 0; nt < 8; nt++) {
            int col = n0 + wn * 64 + nt * 8 + 2 * t;
            float2 bi = *(const float2*)(bias + col);
            *(float2*)(OutF + (size_t)row0 * CC + col) =
                make_float2(acc[mf][nt][0] + bi.x, acc[mf][nt][1] + bi.y);
            *(float2*)(OutF + (size_t)(row0 + 8) * CC + col) =
                make_float2(acc[mf][nt][2] + bi.x, acc[mf][nt][3] + bi.y);
        }
    }
}

// ---------------------------------------------------------------------------
// Flash attention fp16 (R14 unchanged): BM=64, BN=32, D=128, 48KB, 3 CTA/SM.
// ---------------------------------------------------------------------------
#define AKV(s) (16384u + (uint32_t)(s) * 16384u)
#define A_SMEM 49152

__device__ __forceinline__ uint32_t toff(int r, int c) {
    return (uint32_t)(r * 256 + ((c ^ (r & 7)) << 4));
}

__global__ __launch_bounds__(128, 3) void attn_mma()
{
    extern __shared__ char sm[];
    const uint32_t sb = smem_u32(sm);
    const int tid = threadIdx.x, lane = tid & 31, w = tid >> 5;
    const int id = blockIdx.x;
    const int bx = (TT / 64 - 1) - (id >> 5);
    const int hb = id & 31;
    const int h  = hb & 15;
    const int b  = hb >> 4;
    const int i0 = bx * 64;
    const int jtmax = 2 * bx + 1;

    const size_t qbase  = ((size_t)(b * HH + h) * TT + i0) * DD;
    const size_t kvbase = (size_t)b * TT * DD;

#pragma unroll
    for (int i = 0; i < 8; i++) {
        int cid = i * 128 + tid;
        int r = cid >> 4, c = cid & 15;
        CP16(sb + toff(r, c), g_Q + qbase + (size_t)r * DD + c * 8);
    }
#pragma unroll
    for (int i = 0; i < 4; i++) {
        int cid = i * 128 + tid;
        int r = cid >> 4, c = cid & 15;
        size_t gs = kvbase + (size_t)r * DD + c * 8;
        uint32_t off = toff(r, c);
        CP16(sb + AKV(0) + off,        g_K + gs);
        CP16(sb + AKV(0) + 8192 + off, g_V + gs);
    }
    CP_COMMIT();

    const int lrA = lane & 15;
    const int lsA = lane >> 4;
    const int lrB = (lane & 7) + ((lane >> 4) << 3);
    const int csB = (lane >> 3) & 1;
    const int g = lane >> 2, t = lane & 3;

    float oa[16][4];
#pragma unroll
    for (int i = 0; i < 16; i++)
#pragma unroll
        for (int j = 0; j < 4; j++) oa[i][j] = 0.f;
    float m0r = -1e30f, m1r = -1e30f, l0r = 0.f, l1r = 0.f;

    for (int jt = 0; jt <= jtmax; jt++) {
        if (jt > 0) __syncthreads();
        if (jt + 1 <= jtmax) {
            uint32_t stg = AKV((jt + 1) & 1);
#pragma unroll
            for (int i = 0; i < 4; i++) {
                int cid = i * 128 + tid;
                int r = cid >> 4, c = cid & 15;
                size_t gs = kvbase + (size_t)((jt + 1) * 32 + r) * DD + c * 8;
                uint32_t off = toff(r, c);
                CP16(sb + stg + off,        g_K + gs);
                CP16(sb + stg + 8192 + off, g_V + gs);
            }
            CP_COMMIT();
            CP_WAIT(1);
        } else {
            CP_WAIT(0);
        }
        __syncthreads();

        if (32 * jt > i0 + 16 * w + 15) continue;

        const uint32_t kvs = sb + AKV(jt & 1);

        float sa[4][4];
#pragma unroll
        for (int i = 0; i < 4; i++)
#pragma unroll
            for (int j = 0; j < 4; j++) sa[i][j] = 0.f;

#pragma unroll
        for (int ks = 0; ks < 8; ks++) {
            uint32_t a[4];
            LDSM_X4(a[0], a[1], a[2], a[3],
                    sb + toff(16 * w + lrA, 2 * ks + lsA));
#pragma unroll
            for (int np = 0; np < 2; np++) {
                uint32_t k[4];
                LDSM_X4(k[0], k[1], k[2], k[3],
                        kvs + toff(np * 16 + lrB, 2 * ks + csB));
                MMA_F16(sa[2 * np],     a, k[0], k[1]);
                MMA_F16(sa[2 * np + 1], a, k[2], k[3]);
            }
        }

        if (32 * jt + 31 > i0 + 16 * w) {
            int r0g = i0 + 16 * w + g;
#pragma unroll
            for (int nf = 0; nf < 4; nf++) {
                int cg = 32 * jt + nf * 8 + 2 * t;
                if (cg     > r0g)     sa[nf][0] = -1e30f;
                if (cg + 1 > r0g)     sa[nf][1] = -1e30f;
                if (cg     > r0g + 8) sa[nf][2] = -1e30f;
                if (cg + 1 > r0g + 8) sa[nf][3] = -1e30f;
            }
        }

        float mx0 = -1e30f, mx1 = -1e30f;
#pragma unroll
        for (int nf = 0; nf < 4; nf++) {
            mx0 = fmaxf(mx0, fmaxf(sa[nf][0], sa[nf][1]));
            mx1 = fmaxf(mx1, fmaxf(sa[nf][2], sa[nf][3]));
        }
        mx0 = fmaxf(mx0, __shfl_xor_sync(0xffffffffu, mx0, 1));
        mx0 = fmaxf(mx0, __shfl_xor_sync(0xffffffffu, mx0, 2));
        mx1 = fmaxf(mx1, __shfl_xor_sync(0xffffffffu, mx1, 1));
        mx1 = fmaxf(mx1, __shfl_xor_sync(0xffffffffu, mx1, 2));
        float mn0 = fmaxf(m0r, mx0), mn1 = fmaxf(m1r, mx1);

        float sum0 = 0.f, sum1 = 0.f;
#pragma unroll
        for (int nf = 0; nf < 4; nf++) {
            sa[nf][0] = ex2(sa[nf][0] - mn0);
            sa[nf][1] = ex2(sa[nf][1] - mn0);
            sa[nf][2] = ex2(sa[nf][2] - mn1);
            sa[nf][3] = ex2(sa[nf][3] - mn1);
            sum0 += sa[nf][0] + sa[nf][1];
            sum1 += sa[nf][2] + sa[nf][3];
        }
        sum0 += __shfl_xor_sync(0xffffffffu, sum0, 1);
        sum0 += __shfl_xor_sync(0xffffffffu, sum0, 2);
        sum1 += __shfl_xor_sync(0xffffffffu, sum1, 1);
        sum1 += __shfl_xor_sync(0xffffffffu, sum1, 2);

        float scl0 = ex2(m0r - mn0), scl1 = ex2(m1r - mn1);
        l0r = l0r * scl0 + sum0;
        l1r = l1r * scl1 + sum1;
        m0r = mn0; m1r = mn1;

#pragma unroll
        for (int nf = 0; nf < 16; nf++) {
            oa[nf][0] *= scl0; oa[nf][1] *= scl0;
            oa[nf][2] *= scl1; oa[nf][3] *= scl1;
        }

#pragma unroll
        for (int s = 0; s < 2; s++) {
            uint32_t aP[4];
            aP[0] = packh2(sa[2 * s][0],     sa[2 * s][1]);
            aP[1] = packh2(sa[2 * s][2],     sa[2 * s][3]);
            aP[2] = packh2(sa[2 * s + 1][0], sa[2 * s + 1][1]);
            aP[3] = packh2(sa[2 * s + 1][2], sa[2 * s + 1][3]);
#pragma unroll
            for (int np = 0; np < 8; np++) {
                uint32_t v[4];
                LDSM_X4_T(v[0], v[1], v[2], v[3],
                          kvs + 8192 + toff(s * 16 + lrA, 2 * np + lsA));
                MMA_F16(oa[2 * np],     aP, v[0], v[1]);
                MMA_F16(oa[2 * np + 1], aP, v[2], v[3]);
            }
        }
    }

    float inv0 = 1.f / l0r, inv1 = 1.f / l1r;
    size_t or0 = (size_t)(b * TT + i0 + 16 * w + g) * CC + h * DD;
    size_t or1 = or0 + (size_t)8 * CC;
#pragma unroll
    for (int nf = 0; nf < 16; nf++) {
        int col = nf * 8 + 2 * t;
        *(uint32_t*)(g_O + or0 + col) = packh2(oa[nf][0] * inv0, oa[nf][1] * inv0);
        *(uint32_t*)(g_O + or1 + col) = packh2(oa[nf][2] * inv1, oa[nf][3] * inv1);
    }
}

// ---------------------------------------------------------------------------
extern "C" void kernel_launch(void* const* d_in, const int* in_sizes, int n_in,
                              void* d_out, int out_size)
{
    const float* x    = (const float*)d_in[0];
    const float* fcos = (const float*)d_in[1];
    const float* fsin = (const float*)d_in[2];
    const float* wq   = (const float*)d_in[4];
    const float* wqb  = (const float*)d_in[5];
    const float* wk   = (const float*)d_in[6];
    const float* wkb  = (const float*)d_in[7];
    const float* wv   = (const float*)d_in[8];
    const float* wvb  = (const float*)d_in[9];
    const float* wo   = (const float*)d_in[10];
    const float* wob  = (const float*)d_in[11];
    float* out = (float*)d_out;

    cudaFuncSetAttribute(gemm_qkv, cudaFuncAttributeMaxDynamicSharedMemorySize, G2SMEM);
    cudaFuncSetAttribute(gemm_out, cudaFuncAttributeMaxDynamicSharedMemorySize, G2SMEM);
    cudaFuncSetAttribute(attn_mma, cudaFuncAttributeMaxDynamicSharedMemorySize, A_SMEM);

    // 1. fp32 -> fp16 converts + bias pack
    prep_kernel<<<16905, 256>>>(x, wq, wk, wv, wo, wqb, wkb, wvb);

    // 2. fused QKV projection (BK=64, 3-stage, hoisted fragment loads)
    gemm_qkv<<<dim3(NQKV / 128, MTOT / 128), GTHR, G2SMEM>>>(fcos, fsin);

    // 3. flash attention (fp16, 3 CTAs/SM, heavy-first)
    attn_mma<<<1024, 128, A_SMEM>>>();

    // 4. output projection -> d_out (BK=64, 3-stage, hoisted fragment loads)
    gemm_out<<<dim3(CC / 128, MTOT / 128), GTHR, G2SMEM>>>(wob, out);
}